// round 10
// baseline (speedup 1.0000x reference)
#include <cuda_runtime.h>
#include <cuda_fp16.h>
#include <cstdint>
#include <math.h>

#define TT 128
#define BB 64
#define VV 2048
#define HH 1024
#define GG 4096   // 4*HH
#define EOS_ID 1
#define NBLK 128

// ---------------- scratch ----------------
__device__ __half g_xh[(size_t)TT * BB * VV];      // x as fp16
__device__ __half g_wih[(size_t)GG * VV];          // Wi^T [n][k] as fp16
__device__ float  g_pre[(size_t)TT * BB * GG];     // x@Wi + b (fp32)
__device__ __half g_hbuf[2][BB * HH];              // h state fp16 (ping-pong)
__device__ float  g_c[BB * HH];
__device__ unsigned char g_eos[TT * BB];
// hierarchical barrier state
__device__ unsigned g_cnt[8];
__device__ unsigned g_root;
__device__ volatile unsigned g_gen;

// ---------------- helpers ----------------
__device__ __forceinline__ float sigf(float x) { return 1.0f / (1.0f + expf(-x)); }

__device__ __forceinline__ uint32_t sptr(const void* p) {
    return (uint32_t)__cvta_generic_to_shared(p);
}
__device__ __forceinline__ void cp16(uint32_t saddr, const void* g) {
    asm volatile("cp.async.cg.shared.global [%0], [%1], 16;" :: "r"(saddr), "l"(g));
}
__device__ __forceinline__ void cp_commit() { asm volatile("cp.async.commit_group;"); }
template <int N> __device__ __forceinline__ void cp_wait() {
    asm volatile("cp.async.wait_group %0;" :: "n"(N));
}
__device__ __forceinline__ void ldsm4(unsigned& r0, unsigned& r1, unsigned& r2, unsigned& r3,
                                      uint32_t addr) {
    asm volatile("ldmatrix.sync.aligned.m8n8.x4.shared.b16 {%0,%1,%2,%3}, [%4];"
                 : "=r"(r0), "=r"(r1), "=r"(r2), "=r"(r3) : "r"(addr));
}
__device__ __forceinline__ void mma_f16(float* d,
                                        unsigned a0, unsigned a1, unsigned a2, unsigned a3,
                                        unsigned b0, unsigned b1) {
    asm volatile(
        "mma.sync.aligned.m16n8k16.row.col.f32.f16.f16.f32 "
        "{%0,%1,%2,%3}, {%4,%5,%6,%7}, {%8,%9}, {%0,%1,%2,%3};\n"
        : "+f"(d[0]), "+f"(d[1]), "+f"(d[2]), "+f"(d[3])
        : "r"(a0), "r"(a1), "r"(a2), "r"(a3), "r"(b0), "r"(b1));
}

// hierarchical grid barrier: 8 groups of 16 blocks -> 8-way root
__device__ __forceinline__ void grid_sync() {
    __threadfence();
    __syncthreads();
    if (threadIdx.x == 0) {
        unsigned my = g_gen;
        int grp = blockIdx.x >> 4;
        if (atomicAdd(&g_cnt[grp], 1) == 15) {
            if (atomicAdd(&g_root, 1) == 7) {
                g_root = 0;
#pragma unroll
                for (int i = 0; i < 8; ++i) g_cnt[i] = 0;
                __threadfence();
                g_gen = my + 1;
            }
        }
        while (g_gen == my) {}
    }
    __syncthreads();
}

// ---------------- preconvert x -> fp16 ----------------
__global__ void conv_x_kernel(const float* __restrict__ x) {
    size_t i = ((size_t)blockIdx.x * blockDim.x + threadIdx.x) * 8;
    float4 v0 = *reinterpret_cast<const float4*>(x + i);
    float4 v1 = *reinterpret_cast<const float4*>(x + i + 4);
    __half2 h0 = __floats2half2_rn(v0.x, v0.y);
    __half2 h1 = __floats2half2_rn(v0.z, v0.w);
    __half2 h2 = __floats2half2_rn(v1.x, v1.y);
    __half2 h3 = __floats2half2_rn(v1.z, v1.w);
    uint4 u;
    u.x = *(unsigned*)&h0; u.y = *(unsigned*)&h1;
    u.z = *(unsigned*)&h2; u.w = *(unsigned*)&h3;
    *reinterpret_cast<uint4*>(&g_xh[i]) = u;
}

// ---------------- transpose + convert Wi[k][n] -> g_wih[n][k] fp16 --------
__global__ void transp_wi_kernel(const float* __restrict__ Wi) {
    __shared__ __half tile[32][33];
    int n0 = blockIdx.x * 32;
    int k0 = blockIdx.y * 32;
    int tx = threadIdx.x, ty = threadIdx.y;
#pragma unroll
    for (int i = ty; i < 32; i += 8)
        tile[i][tx] = __float2half_rn(Wi[(size_t)(k0 + i) * GG + n0 + tx]);
    __syncthreads();
#pragma unroll
    for (int i = ty; i < 32; i += 8)
        g_wih[(size_t)(n0 + i) * VV + k0 + tx] = tile[tx][i];
}

// ---------------- Phase 1: fp16 mma.sync GEMM, 128x64x64, 256 threads -----
// 8 warps in 4x2 grid, warp tile 32x32 (acc=32 regs), smem 55.3KB
// -> 2 CTAs/SM (16 warps) naturally, no launch_bounds pressure.
__global__ void __launch_bounds__(256) gemm_pre_tc(const float* __restrict__ bias) {
    extern __shared__ __half sm1[];
    __half* As[2] = { sm1,           sm1 + 13824 };
    __half* Bs[2] = { sm1 + 9216,    sm1 + 23040 };

    const int tid = threadIdx.x;
    const int w = tid >> 5, lane = tid & 31;
    const int m0blk = blockIdx.y * 128;
    const int n0blk = blockIdx.x * 64;
    const int wm = (w >> 1) * 32;      // 4 warp-rows
    const int wn = (w & 1) * 32;       // 2 warp-cols
    const int r = lane >> 2, kq = lane & 3;

    const int a_row = (lane & 7) + (lane & 8);
    const int a_k8  = (lane >> 4) << 3;
    const int b_nrow = (lane & 7) + ((lane >> 4) << 3);
    const int b_k8   = ((lane >> 3) & 1) << 3;

    float acc[8][4];
#pragma unroll
    for (int i = 0; i < 8; i++)
#pragma unroll
        for (int j = 0; j < 4; j++) acc[i][j] = 0.0f;

    // A: 1024 cp16/stage (4/thread); B: 512 cp16/stage (2/thread)
    auto stage = [&](int s, int k0) {
#pragma unroll
        for (int q = 0; q < 4; ++q) {
            int f = tid + q * 256;          // 0..1023
            int row = f >> 3;               // 0..127
            int c16 = (f & 7) << 3;
            cp16(sptr(&As[s][row * 72 + c16]),
                 g_xh + (size_t)(m0blk + row) * VV + k0 + c16);
        }
#pragma unroll
        for (int q = 0; q < 2; ++q) {
            int f = tid + q * 256;          // 0..511
            int row = f >> 3;               // 0..63
            int c16 = (f & 7) << 3;
            cp16(sptr(&Bs[s][row * 72 + c16]),
                 g_wih + (size_t)(n0blk + row) * VV + k0 + c16);
        }
        cp_commit();
    };

    stage(0, 0);

    const int NIT = VV / 64;
    for (int it = 0; it < NIT; ++it) {
        int nxt = it + 1;
        if (nxt < NIT) {
            stage(nxt & 1, nxt * 64);
            cp_wait<1>();
        } else {
            cp_wait<0>();
        }
        __syncthreads();

        const __half* Ab = As[it & 1];
        const __half* Bb = Bs[it & 1];
#pragma unroll
        for (int ks = 0; ks < 4; ++ks) {
            int kk = ks * 16;
            unsigned af[2][4];
#pragma unroll
            for (int mt = 0; mt < 2; ++mt)
                ldsm4(af[mt][0], af[mt][1], af[mt][2], af[mt][3],
                      sptr(Ab + (wm + mt * 16 + a_row) * 72 + kk + a_k8));
            unsigned bf[4][2];
            {
                unsigned q0, q1, q2, q3;
                ldsm4(q0, q1, q2, q3, sptr(Bb + (wn + b_nrow) * 72 + kk + b_k8));
                bf[0][0] = q0; bf[0][1] = q1; bf[1][0] = q2; bf[1][1] = q3;
                ldsm4(q0, q1, q2, q3, sptr(Bb + (wn + 16 + b_nrow) * 72 + kk + b_k8));
                bf[2][0] = q0; bf[2][1] = q1; bf[3][0] = q2; bf[3][1] = q3;
            }
#pragma unroll
            for (int mt = 0; mt < 2; ++mt)
#pragma unroll
                for (int nt = 0; nt < 4; ++nt)
                    mma_f16(acc[mt * 4 + nt],
                            af[mt][0], af[mt][1], af[mt][2], af[mt][3],
                            bf[nt][0], bf[nt][1]);
        }
        __syncthreads();
    }

#pragma unroll
    for (int mt = 0; mt < 2; ++mt) {
#pragma unroll
        for (int nt = 0; nt < 4; ++nt) {
            float* a = acc[mt * 4 + nt];
            int col = n0blk + wn + nt * 8 + 2 * kq;
            float b0 = __ldg(&bias[col]), b1 = __ldg(&bias[col + 1]);
            int row0 = m0blk + wm + mt * 16 + r;
            *reinterpret_cast<float2*>(&g_pre[(size_t)row0 * GG + col]) =
                make_float2(a[0] + b0, a[1] + b1);
            *reinterpret_cast<float2*>(&g_pre[(size_t)(row0 + 8) * GG + col]) =
                make_float2(a[2] + b0, a[3] + b1);
        }
    }
}

// ---------------- Phase 2: persistent recurrence (fp16, unchanged R7) -----
// smem: sWh2 @0 (65536) | sH0 @65536 (66560) | sH1 @132096 (66560)
//       | sRed @198656 (8192) | sGpre @206848 (8192) | sEos @215040 (64)
#define SM_SH0  65536
#define SM_SH1  132096
#define SM_SRED 198656
#define SM_GPRE 206848
#define SM_EOS  215040
#define P2_SMEM 215104

__global__ void __launch_bounds__(256) lstm_recurrent(
        const float* __restrict__ Wh,
        const float* __restrict__ h0,
        const float* __restrict__ c0,
        const float* __restrict__ x,
        const unsigned char* __restrict__ eos0,
        float* __restrict__ out) {
    extern __shared__ unsigned char sm2[];
    uint2*  sWh2 = (uint2*)sm2;
    __half* sH[2] = { (__half*)(sm2 + SM_SH0), (__half*)(sm2 + SM_SH1) };
    float*  sRed  = (float*)(sm2 + SM_SRED);
    float*  sGpre = (float*)(sm2 + SM_GPRE);   // [64][32]: row*32 + g*8 + col
    unsigned char* sEos = sm2 + SM_EOS;

    const int tid = threadIdx.x;
    const int w = tid >> 5, lane = tid & 31;
    const int blk = blockIdx.x;
    const int j0 = blk * 8;

    // ---- prologue ----
    if (blk == 0) {  // eos prefix-OR into global
        unsigned char* flags = (unsigned char*)sRed;
        for (int i = tid; i < TT * BB; i += 256) {
            int t = i >> 6, b = i & 63;
            flags[i] = (x[((size_t)t * BB + b) * VV + EOS_ID] != 0.0f) ? 1 : 0;
        }
        __syncthreads();
        if (tid < BB) {
            unsigned char e = eos0[tid] ? 1 : 0;
            for (int t = 0; t < TT; ++t) {
                g_eos[t * BB + tid] = e;
                e |= flags[t * BB + tid];
            }
        }
        __syncthreads();
    }
    // Wh -> smem as pre-built B fragments: sWh2[g*2048 + kk16*32 + lane]
    for (int i = tid; i < 4 * 64 * 32; i += 256) {
        int t = i & 31;
        int kk = (i >> 5) & 63;
        int g = i >> 11;
        int k0 = kk * 16 + (t & 3) * 2;
        int n = t >> 2;
        const float* wp = Wh + (size_t)k0 * GG + g * HH + j0 + n;
        __half2 lo = __floats2half2_rn(wp[0], wp[GG]);
        __half2 hi = __floats2half2_rn(wp[8 * GG], wp[9 * GG]);
        sWh2[i] = make_uint2(*(unsigned*)&lo, *(unsigned*)&hi);
    }
    for (int i = tid; i < BB * 8; i += 256) {
        int b = i >> 3, n = i & 7;
        g_hbuf[0][b * HH + j0 + n] = __float2half_rn(h0[b * HH + j0 + n]);
        g_c[b * HH + j0 + n] = c0[b * HH + j0 + n];
    }
    grid_sync();

    const int half_w = w >> 2;
    const int mt = w & 3;
    const int m0 = mt * 16;
    const int r = lane >> 2;
    const int kq = lane & 3;
    const int a_row = (lane & 7) + (lane & 8);
    const int a_k8 = (lane >> 4) << 3;
    const int lrow = tid >> 2, lc16 = (tid & 3) << 3;

    for (int t = 0; t < TT; ++t) {
        const __half* hin = g_hbuf[t & 1];
        __half* hout = g_hbuf[(t + 1) & 1];
        const float* pre_t = g_pre + (size_t)t * BB * GG;

        // --- group A: g_pre slice + eos + h chunk 0 ---
        {
#pragma unroll
            for (int q = 0; q < 2; ++q) {
                int f = tid * 2 + q;
                int row = f >> 3;
                int seg = f & 7;
                int g = seg >> 1, hf = seg & 1;
                cp16(sptr(&sGpre[row * 32 + g * 8 + hf * 4]),
                     pre_t + (size_t)row * GG + g * HH + j0 + hf * 4);
            }
            if (tid < 4)
                cp16(sptr(sEos + tid * 16), g_eos + t * BB + tid * 16);
            __half* dst = sH[0];
#pragma unroll
            for (int q = 0; q < 16; ++q) {
                int col = lc16 + q * 32;
                cp16(sptr(&dst[lrow * 520 + col]), hin + (size_t)lrow * HH + col);
            }
            cp_commit();
        }
        // --- group B: h chunk 1 ---
        {
            __half* dst = sH[1];
            const __half* src = hin + 512;
#pragma unroll
            for (int q = 0; q < 16; ++q) {
                int col = lc16 + q * 32;
                cp16(sptr(&dst[lrow * 520 + col]), src + (size_t)lrow * HH + col);
            }
            cp_commit();
        }

        float acc[4][4];
#pragma unroll
        for (int g = 0; g < 4; ++g)
#pragma unroll
            for (int j = 0; j < 4; ++j) acc[g][j] = 0.0f;

#pragma unroll
        for (int c = 0; c < 2; ++c) {
            if (c == 0) cp_wait<1>(); else cp_wait<0>();
            __syncthreads();
            const __half* sh = sH[c];
#pragma unroll
            for (int ks = 0; ks < 16; ++ks) {
                int kloc = half_w * 256 + ks * 16;
                unsigned a0, a1, a2, a3;
                ldsm4(a0, a1, a2, a3, sptr(sh + (m0 + a_row) * 520 + kloc + a_k8));
                int kk16 = c * 32 + half_w * 16 + ks;
                const uint2* wb = sWh2 + kk16 * 32 + lane;
#pragma unroll
                for (int g = 0; g < 4; ++g) {
                    uint2 bb = wb[g * 2048];
                    mma_f16(acc[g], a0, a1, a2, a3, bb.x, bb.y);
                }
            }
            if (c == 0) __syncthreads();
        }

        __syncthreads();
        if (half_w == 1) {
#pragma unroll
            for (int g = 0; g < 4; ++g)
                *reinterpret_cast<float4*>(&sRed[((mt * 4 + g) * 32 + lane) * 4]) =
                    make_float4(acc[g][0], acc[g][1], acc[g][2], acc[g][3]);
        }
        __syncthreads();
        if (half_w == 0) {
#pragma unroll
            for (int g = 0; g < 4; ++g) {
                float4 v = *reinterpret_cast<float4*>(&sRed[((mt * 4 + g) * 32 + lane) * 4]);
                acc[g][0] += v.x; acc[g][1] += v.y; acc[g][2] += v.z; acc[g][3] += v.w;
            }
#pragma unroll
            for (int p = 0; p < 4; ++p) {
                int row = m0 + r + ((p >= 2) ? 8 : 0);
                int col = 2 * kq + (p & 1);
                int j = j0 + col;
                const float* gp = &sGpre[row * 32];
                float iv = acc[0][p] + gp[col];
                float fv = acc[1][p] + gp[8 + col];
                float gv = acc[2][p] + gp[16 + col];
                float ov = acc[3][p] + gp[24 + col];
                float cold = g_c[row * HH + j];
                float nc = sigf(fv) * cold + sigf(iv) * tanhf(gv);
                float nh = sigf(ov) * tanhf(nc);
                __stcg(&out[(size_t)t * BB * HH + row * HH + j], nh);
                unsigned char m = sEos[row];
                g_c[row * HH + j] = m ? cold : nc;
                __half hold = hin[row * HH + j];
                hout[row * HH + j] = m ? hold : __float2half_rn(nh);
            }
        }
        grid_sync();
    }
}

// ---------------- launch ----------------
extern "C" void kernel_launch(void* const* d_in, const int* in_sizes, int n_in,
                              void* d_out, int out_size) {
    const float* x    = (const float*)d_in[0];
    const float* Wi   = (const float*)d_in[1];
    const float* Wh   = (const float*)d_in[2];
    const float* bias = (const float*)d_in[3];
    const float* c0   = (const float*)d_in[4];
    const float* h0   = (const float*)d_in[5];
    const unsigned char* eos0 = (const unsigned char*)d_in[6];
    float* out = (float*)d_out;

    conv_x_kernel<<<(TT * BB * VV) / (256 * 8), 256>>>(x);
    transp_wi_kernel<<<dim3(GG / 32, VV / 32), dim3(32, 8)>>>(Wi);

    static int inited = 0;
    const int p1_smem = 2 * 13824 * 2;                // 55296
    if (!inited) {
        cudaFuncSetAttribute(gemm_pre_tc,
                             cudaFuncAttributeMaxDynamicSharedMemorySize, p1_smem);
        cudaFuncSetAttribute(lstm_recurrent,
                             cudaFuncAttributeMaxDynamicSharedMemorySize, P2_SMEM);
        inited = 1;
    }
    gemm_pre_tc<<<dim3(GG / 64, (TT * BB) / 128), 256, p1_smem>>>(bias);
    lstm_recurrent<<<NBLK, 256, P2_SMEM>>>(Wh, h0, c0, x, eos0, out);
}

// round 11
// speedup vs baseline: 1.0217x; 1.0217x over previous
#include <cuda_runtime.h>
#include <cuda_fp16.h>
#include <cstdint>
#include <math.h>

#define TT 128
#define BB 64
#define VV 2048
#define HH 1024
#define GG 4096   // 4*HH
#define EOS_ID 1
#define NBLK 128

// ---------------- scratch ----------------
__device__ __half g_xh[(size_t)TT * BB * VV];      // x as fp16
__device__ __half g_wih[(size_t)GG * VV];          // Wi^T [n][k] as fp16
__device__ float  g_pre[(size_t)TT * BB * GG];     // x@Wi + b (fp32)
__device__ __half g_hbuf[2][BB * HH];              // h state fp16 (ping-pong)
__device__ float  g_c[BB * HH];
__device__ unsigned char g_eos[TT * BB];
// hierarchical barrier state
__device__ unsigned g_cnt[8];
__device__ unsigned g_root;
__device__ volatile unsigned g_gen;

// ---------------- helpers ----------------
__device__ __forceinline__ float sigf(float x) { return 1.0f / (1.0f + expf(-x)); }

__device__ __forceinline__ uint32_t sptr(const void* p) {
    return (uint32_t)__cvta_generic_to_shared(p);
}
__device__ __forceinline__ void cp16(uint32_t saddr, const void* g) {
    asm volatile("cp.async.cg.shared.global [%0], [%1], 16;" :: "r"(saddr), "l"(g));
}
__device__ __forceinline__ void cp_commit() { asm volatile("cp.async.commit_group;"); }
template <int N> __device__ __forceinline__ void cp_wait() {
    asm volatile("cp.async.wait_group %0;" :: "n"(N));
}
__device__ __forceinline__ void ldsm4(unsigned& r0, unsigned& r1, unsigned& r2, unsigned& r3,
                                      uint32_t addr) {
    asm volatile("ldmatrix.sync.aligned.m8n8.x4.shared.b16 {%0,%1,%2,%3}, [%4];"
                 : "=r"(r0), "=r"(r1), "=r"(r2), "=r"(r3) : "r"(addr));
}
__device__ __forceinline__ void mma_f16(float* d,
                                        unsigned a0, unsigned a1, unsigned a2, unsigned a3,
                                        unsigned b0, unsigned b1) {
    asm volatile(
        "mma.sync.aligned.m16n8k16.row.col.f32.f16.f16.f32 "
        "{%0,%1,%2,%3}, {%4,%5,%6,%7}, {%8,%9}, {%0,%1,%2,%3};\n"
        : "+f"(d[0]), "+f"(d[1]), "+f"(d[2]), "+f"(d[3])
        : "r"(a0), "r"(a1), "r"(a2), "r"(a3), "r"(b0), "r"(b1));
}

// hierarchical grid barrier: 8 groups of 16 blocks -> 8-way root
__device__ __forceinline__ void grid_sync() {
    __threadfence();
    __syncthreads();
    if (threadIdx.x == 0) {
        unsigned my = g_gen;
        int grp = blockIdx.x >> 4;
        if (atomicAdd(&g_cnt[grp], 1) == 15) {
            if (atomicAdd(&g_root, 1) == 7) {
                g_root = 0;
#pragma unroll
                for (int i = 0; i < 8; ++i) g_cnt[i] = 0;
                __threadfence();
                g_gen = my + 1;
            }
        }
        while (g_gen == my) {}
    }
    __syncthreads();
}

// ---------------- preconvert x -> fp16 ----------------
__global__ void conv_x_kernel(const float* __restrict__ x) {
    size_t i = ((size_t)blockIdx.x * blockDim.x + threadIdx.x) * 8;
    float4 v0 = *reinterpret_cast<const float4*>(x + i);
    float4 v1 = *reinterpret_cast<const float4*>(x + i + 4);
    __half2 h0 = __floats2half2_rn(v0.x, v0.y);
    __half2 h1 = __floats2half2_rn(v0.z, v0.w);
    __half2 h2 = __floats2half2_rn(v1.x, v1.y);
    __half2 h3 = __floats2half2_rn(v1.z, v1.w);
    uint4 u;
    u.x = *(unsigned*)&h0; u.y = *(unsigned*)&h1;
    u.z = *(unsigned*)&h2; u.w = *(unsigned*)&h3;
    *reinterpret_cast<uint4*>(&g_xh[i]) = u;
}

// ---------------- transpose + convert Wi[k][n] -> g_wih[n][k] fp16 --------
__global__ void transp_wi_kernel(const float* __restrict__ Wi) {
    __shared__ __half tile[32][33];
    int n0 = blockIdx.x * 32;
    int k0 = blockIdx.y * 32;
    int tx = threadIdx.x, ty = threadIdx.y;
#pragma unroll
    for (int i = ty; i < 32; i += 8)
        tile[i][tx] = __float2half_rn(Wi[(size_t)(k0 + i) * GG + n0 + tx]);
    __syncthreads();
#pragma unroll
    for (int i = ty; i < 32; i += 8)
        g_wih[(size_t)(n0 + i) * VV + k0 + tx] = tile[tx][i];
}

// ---------------- Phase 1: fp16 mma GEMM, 128x128x64, 3-stage pipeline ----
// 256 threads, 8 warps (2x4), warp tile 64x32. One __syncthreads per K-iter,
// ldsm frags register-double-buffered across ks to hide LDSM latency.
#define P1_STG 18432   // halfs per stage (A 9216 + B 9216)
__global__ void __launch_bounds__(256) gemm_pre_tc(const float* __restrict__ bias) {
    extern __shared__ __half sm1[];

    const int tid = threadIdx.x;
    const int w = tid >> 5, lane = tid & 31;
    const int m0blk = blockIdx.y * 128;
    const int n0blk = blockIdx.x * 128;
    const int wm = (w >> 2) * 64;
    const int wn = (w & 3) * 32;
    const int r = lane >> 2, kq = lane & 3;

    const int a_row = (lane & 7) + (lane & 8);
    const int a_k8  = (lane >> 4) << 3;
    const int b_nrow = (lane & 7) + ((lane >> 4) << 3);
    const int b_k8   = ((lane >> 3) & 1) << 3;

    float acc[16][4];
#pragma unroll
    for (int i = 0; i < 16; i++)
#pragma unroll
        for (int j = 0; j < 4; j++) acc[i][j] = 0.0f;

    const int lrow = tid >> 3, lc16 = (tid & 7) << 3;

    auto stage = [&](int s, int k0) {
        __half* As = sm1 + s * P1_STG;
        __half* Bs = As + 9216;
#pragma unroll
        for (int q = 0; q < 4; ++q) {
            int row = lrow + q * 32;
            cp16(sptr(&As[row * 72 + lc16]), g_xh + (size_t)(m0blk + row) * VV + k0 + lc16);
            cp16(sptr(&Bs[row * 72 + lc16]), g_wih + (size_t)(n0blk + row) * VV + k0 + lc16);
        }
        cp_commit();
    };

    stage(0, 0);
    stage(1, 64);

    unsigned af[2][4][4];   // [buf][mt][frag]
    unsigned bf[2][4][2];   // [buf][nt][frag]

    const int NIT = VV / 64;
    for (int it = 0; it < NIT; ++it) {
        if (it + 2 < NIT) cp_wait<1>(); else cp_wait<0>();
        __syncthreads();                 // single barrier per iter
        if (it + 2 < NIT) stage((it + 2) % 3, (it + 2) * 64);

        const __half* Ab = sm1 + (it % 3) * P1_STG;
        const __half* Bb = Ab + 9216;

        // prologue frags for ks=0
#pragma unroll
        for (int mt = 0; mt < 4; ++mt)
            ldsm4(af[0][mt][0], af[0][mt][1], af[0][mt][2], af[0][mt][3],
                  sptr(Ab + (wm + mt * 16 + a_row) * 72 + a_k8));
        {
            unsigned q0, q1, q2, q3;
            ldsm4(q0, q1, q2, q3, sptr(Bb + (wn + b_nrow) * 72 + b_k8));
            bf[0][0][0] = q0; bf[0][0][1] = q1; bf[0][1][0] = q2; bf[0][1][1] = q3;
            ldsm4(q0, q1, q2, q3, sptr(Bb + (wn + 16 + b_nrow) * 72 + b_k8));
            bf[0][2][0] = q0; bf[0][2][1] = q1; bf[0][3][0] = q2; bf[0][3][1] = q3;
        }

#pragma unroll
        for (int ks = 0; ks < 4; ++ks) {
            const int cur = ks & 1, nxt = cur ^ 1;
            if (ks < 3) {
                int kk = (ks + 1) * 16;
#pragma unroll
                for (int mt = 0; mt < 4; ++mt)
                    ldsm4(af[nxt][mt][0], af[nxt][mt][1], af[nxt][mt][2], af[nxt][mt][3],
                          sptr(Ab + (wm + mt * 16 + a_row) * 72 + kk + a_k8));
                unsigned q0, q1, q2, q3;
                ldsm4(q0, q1, q2, q3, sptr(Bb + (wn + b_nrow) * 72 + kk + b_k8));
                bf[nxt][0][0] = q0; bf[nxt][0][1] = q1; bf[nxt][1][0] = q2; bf[nxt][1][1] = q3;
                ldsm4(q0, q1, q2, q3, sptr(Bb + (wn + 16 + b_nrow) * 72 + kk + b_k8));
                bf[nxt][2][0] = q0; bf[nxt][2][1] = q1; bf[nxt][3][0] = q2; bf[nxt][3][1] = q3;
            }
#pragma unroll
            for (int mt = 0; mt < 4; ++mt)
#pragma unroll
                for (int nt = 0; nt < 4; ++nt)
                    mma_f16(acc[mt * 4 + nt],
                            af[cur][mt][0], af[cur][mt][1], af[cur][mt][2], af[cur][mt][3],
                            bf[cur][nt][0], bf[cur][nt][1]);
        }
    }

#pragma unroll
    for (int mt = 0; mt < 4; ++mt) {
#pragma unroll
        for (int nt = 0; nt < 4; ++nt) {
            float* a = acc[mt * 4 + nt];
            int col = n0blk + wn + nt * 8 + 2 * kq;
            float b0 = __ldg(&bias[col]), b1 = __ldg(&bias[col + 1]);
            int row0 = m0blk + wm + mt * 16 + r;
            *reinterpret_cast<float2*>(&g_pre[(size_t)row0 * GG + col]) =
                make_float2(a[0] + b0, a[1] + b1);
            *reinterpret_cast<float2*>(&g_pre[(size_t)(row0 + 8) * GG + col]) =
                make_float2(a[2] + b0, a[3] + b1);
        }
    }
}

// ---------------- Phase 2: persistent recurrence (fp16, unchanged R7) -----
// smem: sWh2 @0 (65536) | sH0 @65536 (66560) | sH1 @132096 (66560)
//       | sRed @198656 (8192) | sGpre @206848 (8192) | sEos @215040 (64)
#define SM_SH0  65536
#define SM_SH1  132096
#define SM_SRED 198656
#define SM_GPRE 206848
#define SM_EOS  215040
#define P2_SMEM 215104

__global__ void __launch_bounds__(256) lstm_recurrent(
        const float* __restrict__ Wh,
        const float* __restrict__ h0,
        const float* __restrict__ c0,
        const float* __restrict__ x,
        const unsigned char* __restrict__ eos0,
        float* __restrict__ out) {
    extern __shared__ unsigned char sm2[];
    uint2*  sWh2 = (uint2*)sm2;
    __half* sH[2] = { (__half*)(sm2 + SM_SH0), (__half*)(sm2 + SM_SH1) };
    float*  sRed  = (float*)(sm2 + SM_SRED);
    float*  sGpre = (float*)(sm2 + SM_GPRE);   // [64][32]: row*32 + g*8 + col
    unsigned char* sEos = sm2 + SM_EOS;

    const int tid = threadIdx.x;
    const int w = tid >> 5, lane = tid & 31;
    const int blk = blockIdx.x;
    const int j0 = blk * 8;

    // ---- prologue ----
    if (blk == 0) {  // eos prefix-OR into global
        unsigned char* flags = (unsigned char*)sRed;
        for (int i = tid; i < TT * BB; i += 256) {
            int t = i >> 6, b = i & 63;
            flags[i] = (x[((size_t)t * BB + b) * VV + EOS_ID] != 0.0f) ? 1 : 0;
        }
        __syncthreads();
        if (tid < BB) {
            unsigned char e = eos0[tid] ? 1 : 0;
            for (int t = 0; t < TT; ++t) {
                g_eos[t * BB + tid] = e;
                e |= flags[t * BB + tid];
            }
        }
        __syncthreads();
    }
    // Wh -> smem as pre-built B fragments: sWh2[g*2048 + kk16*32 + lane]
    for (int i = tid; i < 4 * 64 * 32; i += 256) {
        int t = i & 31;
        int kk = (i >> 5) & 63;
        int g = i >> 11;
        int k0 = kk * 16 + (t & 3) * 2;
        int n = t >> 2;
        const float* wp = Wh + (size_t)k0 * GG + g * HH + j0 + n;
        __half2 lo = __floats2half2_rn(wp[0], wp[GG]);
        __half2 hi = __floats2half2_rn(wp[8 * GG], wp[9 * GG]);
        sWh2[i] = make_uint2(*(unsigned*)&lo, *(unsigned*)&hi);
    }
    for (int i = tid; i < BB * 8; i += 256) {
        int b = i >> 3, n = i & 7;
        g_hbuf[0][b * HH + j0 + n] = __float2half_rn(h0[b * HH + j0 + n]);
        g_c[b * HH + j0 + n] = c0[b * HH + j0 + n];
    }
    grid_sync();

    const int half_w = w >> 2;
    const int mt = w & 3;
    const int m0 = mt * 16;
    const int r = lane >> 2;
    const int kq = lane & 3;
    const int a_row = (lane & 7) + (lane & 8);
    const int a_k8 = (lane >> 4) << 3;
    const int lrow = tid >> 2, lc16 = (tid & 3) << 3;

    for (int t = 0; t < TT; ++t) {
        const __half* hin = g_hbuf[t & 1];
        __half* hout = g_hbuf[(t + 1) & 1];
        const float* pre_t = g_pre + (size_t)t * BB * GG;

        // --- group A: g_pre slice + eos + h chunk 0 ---
        {
#pragma unroll
            for (int q = 0; q < 2; ++q) {
                int f = tid * 2 + q;
                int row = f >> 3;
                int seg = f & 7;
                int g = seg >> 1, hf = seg & 1;
                cp16(sptr(&sGpre[row * 32 + g * 8 + hf * 4]),
                     pre_t + (size_t)row * GG + g * HH + j0 + hf * 4);
            }
            if (tid < 4)
                cp16(sptr(sEos + tid * 16), g_eos + t * BB + tid * 16);
            __half* dst = sH[0];
#pragma unroll
            for (int q = 0; q < 16; ++q) {
                int col = lc16 + q * 32;
                cp16(sptr(&dst[lrow * 520 + col]), hin + (size_t)lrow * HH + col);
            }
            cp_commit();
        }
        // --- group B: h chunk 1 ---
        {
            __half* dst = sH[1];
            const __half* src = hin + 512;
#pragma unroll
            for (int q = 0; q < 16; ++q) {
                int col = lc16 + q * 32;
                cp16(sptr(&dst[lrow * 520 + col]), src + (size_t)lrow * HH + col);
            }
            cp_commit();
        }

        float acc[4][4];
#pragma unroll
        for (int g = 0; g < 4; ++g)
#pragma unroll
            for (int j = 0; j < 4; ++j) acc[g][j] = 0.0f;

#pragma unroll
        for (int c = 0; c < 2; ++c) {
            if (c == 0) cp_wait<1>(); else cp_wait<0>();
            __syncthreads();
            const __half* sh = sH[c];
#pragma unroll
            for (int ks = 0; ks < 16; ++ks) {
                int kloc = half_w * 256 + ks * 16;
                unsigned a0, a1, a2, a3;
                ldsm4(a0, a1, a2, a3, sptr(sh + (m0 + a_row) * 520 + kloc + a_k8));
                int kk16 = c * 32 + half_w * 16 + ks;
                const uint2* wb = sWh2 + kk16 * 32 + lane;
#pragma unroll
                for (int g = 0; g < 4; ++g) {
                    uint2 bb = wb[g * 2048];
                    mma_f16(acc[g], a0, a1, a2, a3, bb.x, bb.y);
                }
            }
            if (c == 0) __syncthreads();
        }

        __syncthreads();
        if (half_w == 1) {
#pragma unroll
            for (int g = 0; g < 4; ++g)
                *reinterpret_cast<float4*>(&sRed[((mt * 4 + g) * 32 + lane) * 4]) =
                    make_float4(acc[g][0], acc[g][1], acc[g][2], acc[g][3]);
        }
        __syncthreads();
        if (half_w == 0) {
#pragma unroll
            for (int g = 0; g < 4; ++g) {
                float4 v = *reinterpret_cast<float4*>(&sRed[((mt * 4 + g) * 32 + lane) * 4]);
                acc[g][0] += v.x; acc[g][1] += v.y; acc[g][2] += v.z; acc[g][3] += v.w;
            }
#pragma unroll
            for (int p = 0; p < 4; ++p) {
                int row = m0 + r + ((p >= 2) ? 8 : 0);
                int col = 2 * kq + (p & 1);
                int j = j0 + col;
                const float* gp = &sGpre[row * 32];
                float iv = acc[0][p] + gp[col];
                float fv = acc[1][p] + gp[8 + col];
                float gv = acc[2][p] + gp[16 + col];
                float ov = acc[3][p] + gp[24 + col];
                float cold = g_c[row * HH + j];
                float nc = sigf(fv) * cold + sigf(iv) * tanhf(gv);
                float nh = sigf(ov) * tanhf(nc);
                __stcg(&out[(size_t)t * BB * HH + row * HH + j], nh);
                unsigned char m = sEos[row];
                g_c[row * HH + j] = m ? cold : nc;
                __half hold = hin[row * HH + j];
                hout[row * HH + j] = m ? hold : __float2half_rn(nh);
            }
        }
        grid_sync();
    }
}

// ---------------- launch ----------------
extern "C" void kernel_launch(void* const* d_in, const int* in_sizes, int n_in,
                              void* d_out, int out_size) {
    const float* x    = (const float*)d_in[0];
    const float* Wi   = (const float*)d_in[1];
    const float* Wh   = (const float*)d_in[2];
    const float* bias = (const float*)d_in[3];
    const float* c0   = (const float*)d_in[4];
    const float* h0   = (const float*)d_in[5];
    const unsigned char* eos0 = (const unsigned char*)d_in[6];
    float* out = (float*)d_out;

    conv_x_kernel<<<(TT * BB * VV) / (256 * 8), 256>>>(x);
    transp_wi_kernel<<<dim3(GG / 32, VV / 32), dim3(32, 8)>>>(Wi);

    static int inited = 0;
    const int p1_smem = 3 * P1_STG * 2;               // 110592
    if (!inited) {
        cudaFuncSetAttribute(gemm_pre_tc,
                             cudaFuncAttributeMaxDynamicSharedMemorySize, p1_smem);
        cudaFuncSetAttribute(lstm_recurrent,
                             cudaFuncAttributeMaxDynamicSharedMemorySize, P2_SMEM);
        inited = 1;
    }
    gemm_pre_tc<<<dim3(GG / 128, (TT * BB) / 128), 256, p1_smem>>>(bias);
    lstm_recurrent<<<NBLK, 256, P2_SMEM>>>(Wh, h0, c0, x, eos0, out);
}